// round 14
// baseline (speedup 1.0000x reference)
#include <cuda_runtime.h>
#include <cstdint>

// ============================================================================
// out[b,c] = 8192 - sx[b] - sw[c] + 2*cross[b,c]
//   cross = (weighted x bits u8) @ (w bits s8)^T : M=256, N=4096, K=8192
// GEMM = legacy mma.sync int8 at its accept-rate wall (~44.5us, R4-R10).
// R14 = R13 (packed 1-bit W, best @59.4us) with the bit->byte expansion
// INTERLEAVED into the MMA k-steps (4 pieces), so the expansion ALU issues
// inside the tensor-pipe drain windows instead of stalling each iteration's
// head (R13 lost +5.3us to that).
// ============================================================================

#define THRESH 0.05f

static constexpr int MDIM = 256;
static constexpr int NDIM = 4096;
static constexpr int FDIM = 4096;
static constexpr int KDIM = 8192;          // bit dim
static constexpr int WPROW = KDIM / 8;     // 1024 packed bytes per W row

// ---------------- scratch (device globals) -----------------------------------
static __device__ __align__(128) uint8_t g_xa[(size_t)MDIM * KDIM];   // 2 MB
static __device__ __align__(128) uint8_t g_wp[(size_t)NDIM * WPROW];  // 4 MB
static __device__ float g_sx[MDIM];

// ---------------- PTX helpers ------------------------------------------------
__device__ __forceinline__ uint32_t smem_u32(const void* p) {
    uint32_t a;
    asm("{ .reg .u64 t; cvta.to.shared.u64 t, %1; cvt.u32.u64 %0, t; }"
        : "=r"(a) : "l"(p));
    return a;
}

__device__ __forceinline__ void cp16(uint32_t dst, const void* src) {
    asm volatile("cp.async.cg.shared.global [%0], [%1], 16;"
                 :: "r"(dst), "l"(src) : "memory");
}
#define CP_COMMIT() asm volatile("cp.async.commit_group;" ::: "memory")
#define CP_WAIT2()  asm volatile("cp.async.wait_group 2;" ::: "memory")

__device__ __forceinline__ void mma_u8s8(int32_t* c, const uint32_t* a,
                                         const uint32_t* b) {
    asm volatile(
        "mma.sync.aligned.m16n8k32.row.col.s32.u8.s8.s32 "
        "{%0,%1,%2,%3}, {%4,%5,%6,%7}, {%8,%9}, {%0,%1,%2,%3};"
        : "+r"(c[0]), "+r"(c[1]), "+r"(c[2]), "+r"(c[3])
        : "r"(a[0]), "r"(a[1]), "r"(a[2]), "r"(a[3]), "r"(b[0]), "r"(b[1]));
}

__device__ __forceinline__ void ldsm4(uint32_t& r0, uint32_t& r1, uint32_t& r2,
                                      uint32_t& r3, uint32_t addr) {
    asm volatile("ldmatrix.sync.aligned.m8n8.x4.shared.b16 {%0,%1,%2,%3}, [%4];"
                 : "=r"(r0), "=r"(r1), "=r"(r2), "=r"(r3) : "r"(addr));
}

// ---------------- quant packing (x side: weighted bytes) ----------------------
__device__ __forceinline__ uint32_t qpack2x(float v0, float v1, float wn0,
                                            float wp0, float wn1, float wp1,
                                            float& s) {
    uint32_t b0 = (v0 <= -THRESH) ? (uint32_t)wn0 : 0u;
    uint32_t b1 = (v0 >=  THRESH) ? (uint32_t)wp0 : 0u;
    uint32_t b2 = (v1 <= -THRESH) ? (uint32_t)wn1 : 0u;
    uint32_t b3 = (v1 >=  THRESH) ? (uint32_t)wp1 : 0u;
    s += (float)(b0 + b1 + b2 + b3);
    return b0 | (b1 << 8) | (b2 << 16) | (b3 << 24);
}

// ============================================================================
// quant kernel: blocks [0,256) -> x rows (weighted u8 + sx);
//               blocks [256, 256+4096) -> W rows packed to 1 bit/plane.
// Packed byte p of a row = planes 8p..8p+7, bit i = plane 8p+i.
// ============================================================================
__global__ void __launch_bounds__(256) quant_kernel(const float* __restrict__ x,
                                                    const float* __restrict__ w) {
    const int bid = blockIdx.x;
    const int tid = threadIdx.x;
    const int lane = tid & 31;

    if (bid >= MDIM) {                         // ---- W pack: one row/block ----
        const int row = bid - MDIM;
        const float4* src = (const float4*)(w + (size_t)row * FDIM);
        uint32_t* dst = (uint32_t*)(void*)(g_wp + (size_t)row * WPROW);
#pragma unroll
        for (int j = 0; j < 4; j++) {
            const int c = tid + 256 * j;       // float4 chunk == packed byte idx
            float4 v = src[c];
            uint32_t b =
                ((v.x <= -THRESH) ? 1u : 0u)   | ((v.x >= THRESH) ? 2u : 0u) |
                ((v.y <= -THRESH) ? 4u : 0u)   | ((v.y >= THRESH) ? 8u : 0u) |
                ((v.z <= -THRESH) ? 16u : 0u)  | ((v.z >= THRESH) ? 32u : 0u) |
                ((v.w <= -THRESH) ? 64u : 0u)  | ((v.w >= THRESH) ? 128u : 0u);
            uint32_t val = b << (8 * (lane & 3));
            val |= __shfl_xor_sync(0xffffffffu, val, 1);
            val |= __shfl_xor_sync(0xffffffffu, val, 2);
            if ((lane & 3) == 0) dst[c >> 2] = val;
        }
        return;
    }

    // ---- x row quant (weighted bytes) + row sum ----------------------------
    const float4* src = (const float4*)(x + (size_t)bid * FDIM);
    uint2* dst = (uint2*)(void*)(g_xa + (size_t)bid * KDIM);
    float s = 0.0f;
    float4 v[4];
#pragma unroll
    for (int j = 0; j < 4; j++) v[j] = src[tid + j * 256];
#pragma unroll
    for (int j = 0; j < 4; j++) {
        uint2 o;
        o.x = qpack2x(v[j].x, v[j].y, 128.f, 64.f, 32.f, 16.f, s);
        o.y = qpack2x(v[j].z, v[j].w,   8.f,  4.f,  2.f,  1.f, s);
        dst[tid + j * 256] = o;
    }
    __shared__ float red[256];
    red[tid] = s;
    __syncthreads();
    for (int off = 128; off > 0; off >>= 1) {
        if (tid < off) red[tid] += red[tid + off];
        __syncthreads();
    }
    if (tid == 0) g_sx[bid] = red[0];
}

// ============================================================================
// GEMM: BM=64, BN=128, BK=128; A = 4-stage cp.async; B = packed LDG ->
// in-SMEM bit->byte expansion INTERLEAVED into k-steps, double-buffered.
// 256 thr = 8 warps 2(M) x 4(N), warp tile 32x32, STRIDE=144. Grid (32,4).
// ============================================================================

static constexpr int BM = 64;
static constexpr int BN = 128;
static constexpr int BK = 128;
static constexpr int KITERS = KDIM / BK;        // 64
static constexpr int NSTAGES = 4;
static constexpr int STRIDE = 144;
static constexpr int A_SZ = BM * STRIDE;        // 9216
static constexpr int B_OFF = NSTAGES * A_SZ;    // 36864
static constexpr int B_SZ = BN * STRIDE;        // 18432
static constexpr int SMEM_BYTES = B_OFF + 2 * B_SZ;  // 73728

__global__ void __launch_bounds__(256, 1)
qgemm_kernel(float* __restrict__ out) {
    extern __shared__ char smem[];
    __shared__ float swacc[BN];

    const uint32_t sb = smem_u32(smem);
    const int tid = threadIdx.x;
    const int wid = tid >> 5;
    const int lane = tid & 31;
    const int wm = wid & 1;
    const int wn = wid >> 1;
    const int n0 = blockIdx.x * BN;
    const int m0 = blockIdx.y * BM;

    // ---- A cp.async: 2 chunks/thread ---------------------------------------
    const uint8_t* a_src[2]; uint32_t a_dst[2];
#pragma unroll
    for (int i = 0; i < 2; i++) {
        int q = tid + i * 256;
        int r = q >> 3, kc = q & 7;
        a_src[i] = g_xa + (size_t)(m0 + r) * KDIM + kc * 16;
        a_dst[i] = (uint32_t)(r * STRIDE + kc * 16);
    }
    auto load_stage = [&](int s) {
        const uint32_t base = sb + (uint32_t)(s & (NSTAGES - 1)) * A_SZ;
        const int ko = s * BK;
#pragma unroll
        for (int i = 0; i < 2; i++) cp16(base + a_dst[i], a_src[i] + ko);
    };

    // ---- B expansion: thread covers (row tid>>1, 64-byte half tid&1) -------
    // Split into 4 pieces of 2 packed bytes each; piece p writes output
    // bytes [16p, 16p+16) of this thread's 64-byte span (verified vs R13).
    const int brow = tid >> 1;
    const int h    = tid & 1;
    const uint8_t* wp_src = g_wp + (size_t)(n0 + brow) * WPROW + h * 8;
    const uint32_t bds = (uint32_t)(B_OFF + brow * STRIDE + h * 64);
    int isw = 0;
    auto expand_piece = [&](uint2 pk, int slot, int piece) {
        char* base = smem + bds + slot * B_SZ;
        const uint32_t wv = (piece < 2) ? pk.x : pk.y;
        const uint32_t sh = (uint32_t)(piece & 1) * 16u;
        const uint32_t b0 = (wv >> sh) & 0xFFu;
        const uint32_t b1 = (wv >> (sh + 8)) & 0xFFu;
        isw += (int)(__brev(b0) >> 24) + (int)(__brev(b1) >> 24);
        uint4 o;
        o.x = ((b0 & 0xFu) * 0x00204081u) & 0x01010101u;
        o.y = ((b0 >> 4)   * 0x00204081u) & 0x01010101u;
        o.z = ((b1 & 0xFu) * 0x00204081u) & 0x01010101u;
        o.w = ((b1 >> 4)   * 0x00204081u) & 0x01010101u;
        *(uint4*)(base + piece * 16) = o;
    };

    // ---- ldmatrix per-lane offsets -----------------------------------------
    const int g  = lane >> 3;
    const int lr = lane & 7;
    uint32_t a_lds[2];
#pragma unroll
    for (int mf = 0; mf < 2; mf++)
        a_lds[mf] = (uint32_t)((wm * 32 + mf * 16 + lr + (g & 1) * 8) * STRIDE
                               + (g >> 1) * 16);
    uint32_t b_lds[2];
#pragma unroll
    for (int p = 0; p < 2; p++)
        b_lds[p] = (uint32_t)((wn * 32 + p * 16 + lr + (g >> 1) * 8) * STRIDE
                              + (g & 1) * 16);

    int32_t acc[2][4][4];
#pragma unroll
    for (int mf = 0; mf < 2; mf++)
#pragma unroll
        for (int nf = 0; nf < 4; nf++)
#pragma unroll
            for (int r = 0; r < 4; r++) acc[mf][nf][r] = 0;

    uint32_t afr[2][2][4];
    uint32_t bfr[2][4][2];
    auto load_frags = [&](uint32_t abase, uint32_t bbase, int ks, int buf) {
        const uint32_t kb = (uint32_t)(ks * 32);
#pragma unroll
        for (int mf = 0; mf < 2; mf++)
            ldsm4(afr[buf][mf][0], afr[buf][mf][1], afr[buf][mf][2],
                  afr[buf][mf][3], abase + a_lds[mf] + kb);
#pragma unroll
        for (int p = 0; p < 2; p++)
            ldsm4(bfr[buf][2*p][0], bfr[buf][2*p][1],
                  bfr[buf][2*p+1][0], bfr[buf][2*p+1][1],
                  bbase + b_lds[p] + kb);
    };

    // ---- prologue ----------------------------------------------------------
#pragma unroll
    for (int s = 0; s < NSTAGES - 1; ++s) { load_stage(s); CP_COMMIT(); }
    {
        uint2 p0 = *(const uint2*)wp_src;       // packed chunk 0
#pragma unroll
        for (int p = 0; p < 4; p++) expand_piece(p0, 0, p);
    }
    uint2 pk = *(const uint2*)(wp_src + 16);    // packed chunk 1

    // ---- mainloop ----------------------------------------------------------
    // Invariant at iteration it: slot it&1 holds chunk it; pk holds packed
    // chunk it+1, expanded piecewise into slot (it+1)&1 during the k-steps.
    for (int it = 0; it < KITERS; ++it) {
        CP_WAIT2();
        __syncthreads();     // A stage it + B slot it&1 visible; old slots free

        uint2 pk_next;
        if (it + 2 < KITERS) pk_next = *(const uint2*)(wp_src + (it + 2) * 16);
        if (it + NSTAGES - 1 < KITERS) load_stage(it + NSTAGES - 1);
        CP_COMMIT();

        const uint32_t abase = sb + (uint32_t)(it & (NSTAGES - 1)) * A_SZ;
        const uint32_t bbase = sb + (uint32_t)(B_OFF + (it & 1) * B_SZ);
        const bool do_exp = (it + 1 < KITERS);
        const int eslot = (it + 1) & 1;

        load_frags(abase, bbase, 0, 0);
#pragma unroll
        for (int ks = 0; ks < BK / 32; ++ks) {
            const int cur = ks & 1;
            if (ks < BK / 32 - 1) load_frags(abase, bbase, ks + 1, cur ^ 1);
#pragma unroll
            for (int mf = 0; mf < 2; mf++)
#pragma unroll
                for (int nf = 0; nf < 4; nf++)
                    mma_u8s8(acc[mf][nf], afr[cur][mf], bfr[cur][nf]);
            if (do_exp) expand_piece(pk, eslot, ks);   // rides the MMA drain
        }
        pk = pk_next;
    }

    // ---- sw: pair (tid, tid^1) covers a full W row over all chunks ---------
    const int sw2 = isw + __shfl_xor_sync(0xffffffffu, isw, 1);
    if (h == 0) swacc[brow] = (float)sw2;
    __syncthreads();

    // ---- epilogue: out = 8192 - sx[m] - sw[n] + 2*acc  (exact integers) ----
#pragma unroll
    for (int mf = 0; mf < 2; mf++) {
        const int r0 = m0 + wm * 32 + mf * 16 + (lane >> 2);
        const float bx0 = 8192.0f - g_sx[r0];
        const float bx1 = 8192.0f - g_sx[r0 + 8];
#pragma unroll
        for (int nf = 0; nf < 4; nf++) {
            const int cl = wn * 32 + nf * 8 + (lane & 3) * 2;
            const float sw0 = swacc[cl], sw1 = swacc[cl + 1];
            const int col = n0 + cl;
            float2 v0, v1;
            v0.x = bx0 - sw0 + 2.0f * (float)acc[mf][nf][0];
            v0.y = bx0 - sw1 + 2.0f * (float)acc[mf][nf][1];
            v1.x = bx1 - sw0 + 2.0f * (float)acc[mf][nf][2];
            v1.y = bx1 - sw1 + 2.0f * (float)acc[mf][nf][3];
            *(float2*)(out + (size_t)r0 * NDIM + col) = v0;
            *(float2*)(out + (size_t)(r0 + 8) * NDIM + col) = v1;
        }
    }
}

// ============================================================================
// launcher
// ============================================================================
extern "C" void kernel_launch(void* const* d_in, const int* in_sizes, int n_in,
                              void* d_out, int out_size) {
    (void)in_sizes; (void)n_in; (void)out_size;
    const float* x = (const float*)d_in[0];   // [256, 4096]
    const float* w = (const float*)d_in[1];   // [4096, 4096]
    float* out = (float*)d_out;               // [256, 4096]

    quant_kernel<<<MDIM + NDIM, 256>>>(x, w);

    cudaFuncSetAttribute(qgemm_kernel,
                         cudaFuncAttributeMaxDynamicSharedMemorySize, SMEM_BYTES);
    dim3 grid(NDIM / BN, MDIM / BM);          // (32, 4) = 128 CTAs
    qgemm_kernel<<<grid, 256, SMEM_BYTES>>>(out);
}

// round 15
// speedup vs baseline: 1.0463x; 1.0463x over previous
#include <cuda_runtime.h>
#include <cstdint>

// ============================================================================
// out[b,c] = 8192 - sx[b] - sw[c] + 2*cross[b,c]
//   cross = (weighted x bits u8) @ (w bits s8)^T : M=256, N=4096, K=8192
// GEMM = legacy mma.sync int8 at its accept-rate wall (~44.5us).
// R15: packed 1-bit W (4MB) kept; GEMM tile flipped to BM=128/BN=64 so the
// in-kernel bit->byte expansion covers HALF the bytes per CTA (and 2x not 4x
// chip-wide duplication). Expansion upfront (R13 placement; R14 interleave
// regressed). Predicted expansion penalty 5.3 -> ~2.6us.
// ============================================================================

#define THRESH 0.05f

static constexpr int MDIM = 256;
static constexpr int NDIM = 4096;
static constexpr int FDIM = 4096;
static constexpr int KDIM = 8192;          // bit dim
static constexpr int WPROW = KDIM / 8;     // 1024 packed bytes per W row

// ---------------- scratch (device globals) -----------------------------------
static __device__ __align__(128) uint8_t g_xa[(size_t)MDIM * KDIM];   // 2 MB
static __device__ __align__(128) uint8_t g_wp[(size_t)NDIM * WPROW];  // 4 MB
static __device__ float g_sx[MDIM];

// ---------------- PTX helpers ------------------------------------------------
__device__ __forceinline__ uint32_t smem_u32(const void* p) {
    uint32_t a;
    asm("{ .reg .u64 t; cvta.to.shared.u64 t, %1; cvt.u32.u64 %0, t; }"
        : "=r"(a) : "l"(p));
    return a;
}

__device__ __forceinline__ void cp16(uint32_t dst, const void* src) {
    asm volatile("cp.async.cg.shared.global [%0], [%1], 16;"
                 :: "r"(dst), "l"(src) : "memory");
}
#define CP_COMMIT() asm volatile("cp.async.commit_group;" ::: "memory")
#define CP_WAIT2()  asm volatile("cp.async.wait_group 2;" ::: "memory")

__device__ __forceinline__ void mma_u8s8(int32_t* c, const uint32_t* a,
                                         const uint32_t* b) {
    asm volatile(
        "mma.sync.aligned.m16n8k32.row.col.s32.u8.s8.s32 "
        "{%0,%1,%2,%3}, {%4,%5,%6,%7}, {%8,%9}, {%0,%1,%2,%3};"
        : "+r"(c[0]), "+r"(c[1]), "+r"(c[2]), "+r"(c[3])
        : "r"(a[0]), "r"(a[1]), "r"(a[2]), "r"(a[3]), "r"(b[0]), "r"(b[1]));
}

__device__ __forceinline__ void ldsm4(uint32_t& r0, uint32_t& r1, uint32_t& r2,
                                      uint32_t& r3, uint32_t addr) {
    asm volatile("ldmatrix.sync.aligned.m8n8.x4.shared.b16 {%0,%1,%2,%3}, [%4];"
                 : "=r"(r0), "=r"(r1), "=r"(r2), "=r"(r3) : "r"(addr));
}

// ---------------- quant packing (x side: weighted bytes) ----------------------
__device__ __forceinline__ uint32_t qpack2x(float v0, float v1, float wn0,
                                            float wp0, float wn1, float wp1,
                                            float& s) {
    uint32_t b0 = (v0 <= -THRESH) ? (uint32_t)wn0 : 0u;
    uint32_t b1 = (v0 >=  THRESH) ? (uint32_t)wp0 : 0u;
    uint32_t b2 = (v1 <= -THRESH) ? (uint32_t)wn1 : 0u;
    uint32_t b3 = (v1 >=  THRESH) ? (uint32_t)wp1 : 0u;
    s += (float)(b0 + b1 + b2 + b3);
    return b0 | (b1 << 8) | (b2 << 16) | (b3 << 24);
}

// ============================================================================
// quant kernel (unchanged from R13, passing): blocks [0,256) -> x rows
// (weighted u8 + sx); blocks [256,256+4096) -> W rows packed 1 bit/plane.
// Packed byte p of a row = planes 8p..8p+7, bit i = plane 8p+i.
// ============================================================================
__global__ void __launch_bounds__(256) quant_kernel(const float* __restrict__ x,
                                                    const float* __restrict__ w) {
    const int bid = blockIdx.x;
    const int tid = threadIdx.x;
    const int lane = tid & 31;

    if (bid >= MDIM) {                         // ---- W pack: one row/block ----
        const int row = bid - MDIM;
        const float4* src = (const float4*)(w + (size_t)row * FDIM);
        uint32_t* dst = (uint32_t*)(void*)(g_wp + (size_t)row * WPROW);
#pragma unroll
        for (int j = 0; j < 4; j++) {
            const int c = tid + 256 * j;       // float4 chunk == packed byte idx
            float4 v = src[c];
            uint32_t b =
                ((v.x <= -THRESH) ? 1u : 0u)   | ((v.x >= THRESH) ? 2u : 0u) |
                ((v.y <= -THRESH) ? 4u : 0u)   | ((v.y >= THRESH) ? 8u : 0u) |
                ((v.z <= -THRESH) ? 16u : 0u)  | ((v.z >= THRESH) ? 32u : 0u) |
                ((v.w <= -THRESH) ? 64u : 0u)  | ((v.w >= THRESH) ? 128u : 0u);
            uint32_t val = b << (8 * (lane & 3));
            val |= __shfl_xor_sync(0xffffffffu, val, 1);
            val |= __shfl_xor_sync(0xffffffffu, val, 2);
            if ((lane & 3) == 0) dst[c >> 2] = val;
        }
        return;
    }

    // ---- x row quant (weighted bytes) + row sum ----------------------------
    const float4* src = (const float4*)(x + (size_t)bid * FDIM);
    uint2* dst = (uint2*)(void*)(g_xa + (size_t)bid * KDIM);
    float s = 0.0f;
    float4 v[4];
#pragma unroll
    for (int j = 0; j < 4; j++) v[j] = src[tid + j * 256];
#pragma unroll
    for (int j = 0; j < 4; j++) {
        uint2 o;
        o.x = qpack2x(v[j].x, v[j].y, 128.f, 64.f, 32.f, 16.f, s);
        o.y = qpack2x(v[j].z, v[j].w,   8.f,  4.f,  2.f,  1.f, s);
        dst[tid + j * 256] = o;
    }
    __shared__ float red[256];
    red[tid] = s;
    __syncthreads();
    for (int off = 128; off > 0; off >>= 1) {
        if (tid < off) red[tid] += red[tid + off];
        __syncthreads();
    }
    if (tid == 0) g_sx[bid] = red[0];
}

// ============================================================================
// GEMM: BM=128, BN=64, BK=128; A = 4-stage cp.async (4 chunks/thread, the
// mapping proven as R4's B loader); B = packed LDG -> upfront in-SMEM
// expansion (4 bytes/thread/iter), double-buffered.
// 256 thr = 8 warps 4(M) x 2(N); warp tile 32x32 (same MMA core as R5).
// STRIDE=144 (ldmatrix conflict-free). Grid (64,2) = 128 CTAs.
// ============================================================================

static constexpr int BM = 128;
static constexpr int BN = 64;
static constexpr int BK = 128;
static constexpr int KITERS = KDIM / BK;        // 64
static constexpr int NSTAGES = 4;
static constexpr int STRIDE = 144;
static constexpr int A_SZ = BM * STRIDE;        // 18432
static constexpr int B_OFF = NSTAGES * A_SZ;    // 73728
static constexpr int B_SZ = BN * STRIDE;        // 9216
static constexpr int SMEM_BYTES = B_OFF + 2 * B_SZ;  // 92160

__global__ void __launch_bounds__(256, 1)
qgemm_kernel(float* __restrict__ out) {
    extern __shared__ char smem[];
    __shared__ float swacc[BN];

    const uint32_t sb = smem_u32(smem);
    const int tid = threadIdx.x;
    const int wid = tid >> 5;
    const int lane = tid & 31;
    const int wm = wid >> 1;         // 0..3 (M), 32 rows each
    const int wn = wid & 1;          // 0..1 (N), 32 cols each
    const int n0 = blockIdx.x * BN;
    const int m0 = blockIdx.y * BM;

    // ---- A cp.async: 128 rows x 8 x 16B = 1024 chunks -> 4/thread ----------
    const uint8_t* a_src[4]; uint32_t a_dst[4];
#pragma unroll
    for (int i = 0; i < 4; i++) {
        int q = tid + i * 256;
        int r = q >> 3, kc = q & 7;
        a_src[i] = g_xa + (size_t)(m0 + r) * KDIM + kc * 16;
        a_dst[i] = (uint32_t)(r * STRIDE + kc * 16);
    }
    auto load_stage = [&](int s) {
        const uint32_t base = sb + (uint32_t)(s & (NSTAGES - 1)) * A_SZ;
        const int ko = s * BK;
#pragma unroll
        for (int i = 0; i < 4; i++) cp16(base + a_dst[i], a_src[i] + ko);
    };

    // ---- B expansion: thread covers (row tid>>2, 32-byte quarter tid&3) ----
    // Per iter: one uint32 packed load (4 bytes -> 32 output bytes, 2 STS.128).
    const int brow = tid >> 2;                 // B row 0..63
    const int bq   = tid & 3;                  // quarter
    const uint8_t* wp_src = g_wp + (size_t)(n0 + brow) * WPROW + bq * 4;
    const uint32_t bds = (uint32_t)(B_OFF + brow * STRIDE + bq * 32);
    int isw = 0;
    auto expand = [&](uint32_t pk, int slot) {
        char* base = smem + bds + slot * B_SZ;
#pragma unroll
        for (int half = 0; half < 2; half++) {
            const uint32_t b0 = (pk >> (16 * half)) & 0xFFu;
            const uint32_t b1 = (pk >> (16 * half + 8)) & 0xFFu;
            isw += (int)(__brev(b0) >> 24) + (int)(__brev(b1) >> 24);
            uint4 o;
            o.x = ((b0 & 0xFu) * 0x00204081u) & 0x01010101u;
            o.y = ((b0 >> 4)   * 0x00204081u) & 0x01010101u;
            o.z = ((b1 & 0xFu) * 0x00204081u) & 0x01010101u;
            o.w = ((b1 >> 4)   * 0x00204081u) & 0x01010101u;
            *(uint4*)(base + half * 16) = o;
        }
    };

    // ---- ldmatrix per-lane offsets -----------------------------------------
    const int g  = lane >> 3;
    const int lr = lane & 7;
    uint32_t a_lds[2];
#pragma unroll
    for (int mf = 0; mf < 2; mf++)
        a_lds[mf] = (uint32_t)((wm * 32 + mf * 16 + lr + (g & 1) * 8) * STRIDE
                               + (g >> 1) * 16);
    uint32_t b_lds[2];
#pragma unroll
    for (int p = 0; p < 2; p++)
        b_lds[p] = (uint32_t)(B_OFF + (wn * 32 + p * 16 + lr + (g >> 1) * 8) * STRIDE
                              + (g & 1) * 16);

    int32_t acc[2][4][4];
#pragma unroll
    for (int mf = 0; mf < 2; mf++)
#pragma unroll
        for (int nf = 0; nf < 4; nf++)
#pragma unroll
            for (int r = 0; r < 4; r++) acc[mf][nf][r] = 0;

    uint32_t afr[2][2][4];
    uint32_t bfr[2][4][2];
    auto load_frags = [&](uint32_t abase, uint32_t bbase, int ks, int buf) {
        const uint32_t kb = (uint32_t)(ks * 32);
#pragma unroll
        for (int mf = 0; mf < 2; mf++)
            ldsm4(afr[buf][mf][0], afr[buf][mf][1], afr[buf][mf][2],
                  afr[buf][mf][3], abase + a_lds[mf] + kb);
#pragma unroll
        for (int p = 0; p < 2; p++)
            ldsm4(bfr[buf][2*p][0], bfr[buf][2*p][1],
                  bfr[buf][2*p+1][0], bfr[buf][2*p+1][1],
                  bbase + b_lds[p] + kb);
    };

    // ---- prologue ----------------------------------------------------------
#pragma unroll
    for (int s = 0; s < NSTAGES - 1; ++s) { load_stage(s); CP_COMMIT(); }
    expand(*(const uint32_t*)wp_src, 0);        // B chunk 0 -> slot 0
    uint32_t pk = *(const uint32_t*)(wp_src + 16);  // packed chunk 1

    // ---- mainloop ----------------------------------------------------------
    for (int it = 0; it < KITERS; ++it) {
        CP_WAIT2();
        __syncthreads();     // A stage it + B slot it&1 visible; old slots free

        if (it + 1 < KITERS) expand(pk, (it + 1) & 1);       // upfront (R13)
        if (it + 2 < KITERS) pk = *(const uint32_t*)(wp_src + (it + 2) * 16);
        if (it + NSTAGES - 1 < KITERS) load_stage(it + NSTAGES - 1);
        CP_COMMIT();

        const uint32_t abase = sb + (uint32_t)(it & (NSTAGES - 1)) * A_SZ;
        const uint32_t bbase = sb + (uint32_t)((it & 1) * B_SZ);
        load_frags(abase, bbase, 0, 0);
#pragma unroll
        for (int ks = 0; ks < BK / 32; ++ks) {
            const int cur = ks & 1;
            if (ks < BK / 32 - 1) load_frags(abase, bbase, ks + 1, cur ^ 1);
#pragma unroll
            for (int mf = 0; mf < 2; mf++)
#pragma unroll
                for (int nf = 0; nf < 4; nf++)
                    mma_u8s8(acc[mf][nf], afr[cur][mf], bfr[cur][nf]);
        }
    }

    // ---- sw: lanes r*4+q, q=0..3, cover a full W row over all chunks -------
    isw += __shfl_xor_sync(0xffffffffu, isw, 1);
    isw += __shfl_xor_sync(0xffffffffu, isw, 2);
    if (bq == 0) swacc[brow] = (float)isw;
    __syncthreads();

    // ---- epilogue: out = 8192 - sx[m] - sw[n] + 2*acc  (exact integers) ----
#pragma unroll
    for (int mf = 0; mf < 2; mf++) {
        const int r0 = m0 + wm * 32 + mf * 16 + (lane >> 2);
        const float bx0 = 8192.0f - g_sx[r0];
        const float bx1 = 8192.0f - g_sx[r0 + 8];
#pragma unroll
        for (int nf = 0; nf < 4; nf++) {
            const int cl = wn * 32 + nf * 8 + (lane & 3) * 2;   // local col < 64
            const float sw0 = swacc[cl], sw1 = swacc[cl + 1];
            const int col = n0 + cl;
            float2 v0, v1;
            v0.x = bx0 - sw0 + 2.0f * (float)acc[mf][nf][0];
            v0.y = bx0 - sw1 + 2.0f * (float)acc[mf][nf][1];
            v1.x = bx1 - sw0 + 2.0f * (float)acc[mf][nf][2];
            v1.y = bx1 - sw1 + 2.0f * (float)acc[mf][nf][3];
            *(float2*)(out + (size_t)r0 * NDIM + col) = v0;
            *(float2*)(out + (size_t)(r0 + 8) * NDIM + col) = v1;
        }
    }
}

// ============================================================================
// launcher
// ============================================================================
extern "C" void kernel_launch(void* const* d_in, const int* in_sizes, int n_in,
                              void* d_out, int out_size) {
    (void)in_sizes; (void)n_in; (void)out_size;
    const float* x = (const float*)d_in[0];   // [256, 4096]
    const float* w = (const float*)d_in[1];   // [4096, 4096]
    float* out = (float*)d_out;               // [256, 4096]

    quant_kernel<<<MDIM + NDIM, 256>>>(x, w);

    cudaFuncSetAttribute(qgemm_kernel,
                         cudaFuncAttributeMaxDynamicSharedMemorySize, SMEM_BYTES);
    dim3 grid(NDIM / BN, MDIM / BM);          // (64, 2) = 128 CTAs
    qgemm_kernel<<<grid, 256, SMEM_BYTES>>>(out);
}